// round 3
// baseline (speedup 1.0000x reference)
#include <cuda_runtime.h>
#include <cstdint>

// ---------------------------------------------------------------------------
// MambaBlock: rmsnorm -> [gate|p] GEMM (tf32 mma) -> fused scan -> out GEMM
// Shapes: B=4, S=4096, D=1024, H=16, Dstate=64
// ---------------------------------------------------------------------------

#define MAX_M 16384

// scratch (device globals; referenced ONLY from device code)
__device__ float g_xn[(size_t)MAX_M * 1024];     // xn, later overwritten by "mixed"
__device__ float g_proj[(size_t)MAX_M * 4096];   // [gate(1024) | p(3072)] per token

// ---------------------------------------------------------------------------
__device__ __forceinline__ uint32_t f2tf32(float x) {
    uint32_t r;
    asm("cvt.rna.tf32.f32 %0, %1;" : "=r"(r) : "f"(x));
    return r;
}
__device__ __forceinline__ void mma8(float* c,
                                     uint32_t a0, uint32_t a1, uint32_t a2, uint32_t a3,
                                     uint32_t b0, uint32_t b1) {
    asm volatile(
        "mma.sync.aligned.m16n8k8.row.col.f32.tf32.tf32.f32 "
        "{%0,%1,%2,%3},{%4,%5,%6,%7},{%8,%9},{%0,%1,%2,%3};"
        : "+f"(c[0]), "+f"(c[1]), "+f"(c[2]), "+f"(c[3])
        : "r"(a0), "r"(a1), "r"(a2), "r"(a3), "r"(b0), "r"(b1));
}
__device__ __forceinline__ void cpasync16(uint32_t saddr, const void* g) {
    asm volatile("cp.async.cg.shared.global [%0], [%1], 16;" :: "r"(saddr), "l"(g));
}
__device__ __forceinline__ float sigmoidf_(float v) {
    return 1.0f / (1.0f + __expf(-v));
}

// ---------------------------------------------------------------------------
// RMSNorm: one block per token, 256 threads x float4
__global__ void rmsnorm_kernel(const float* __restrict__ x, const float* __restrict__ w) {
    const int row = blockIdx.x;
    const int tid = threadIdx.x;
    const float4* xr = (const float4*)(x + (size_t)row * 1024);
    float4 v = xr[tid];
    float ss = v.x * v.x + v.y * v.y + v.z * v.z + v.w * v.w;
    #pragma unroll
    for (int o = 16; o; o >>= 1) ss += __shfl_xor_sync(0xffffffff, ss, o);
    __shared__ float sred[8];
    const int lane = tid & 31, warp = tid >> 5;
    if (lane == 0) sred[warp] = ss;
    __syncthreads();
    if (warp == 0) {
        float t = sred[lane & 7];
        #pragma unroll
        for (int o = 4; o; o >>= 1) t += __shfl_xor_sync(0xffffffff, t, o);
        if (lane == 0) sred[0] = t;
    }
    __syncthreads();
    const float rinv = rsqrtf(sred[0] * (1.0f / 1024.0f) + 1e-6f);
    const float4 wv = ((const float4*)w)[tid];
    float4 o;
    o.x = v.x * rinv * wv.x;
    o.y = v.y * rinv * wv.y;
    o.z = v.z * rinv * wv.z;
    o.w = v.w * rinv * wv.w;
    ((float4*)(g_xn + (size_t)row * 1024))[tid] = o;
}

// ---------------------------------------------------------------------------
// TF32 GEMM, BM=BN=128, BK=16, 256 threads, warp tile 64x32 (mma m16n8k8).
// EPI==1: A=g_xn, B = [Wg | Wp] split at col 1024, +bias, sigmoid on gate and
//         delta cols, out = g_proj (device global, ld 4096).
// EPI==2: A=g_xn(mixed), B = Wo, +bo + residual x, out = d_out (ld 1024).
constexpr int ASTR = 20;   // A smem stride (16 + 4 pad)
constexpr int BSTR = 136;  // B smem stride (128 + 8 pad)

template<int EPI>
__global__ __launch_bounds__(256, 2)
void gemm_tf32(const float* __restrict__ B0, const float* __restrict__ B1,
               const float* __restrict__ bias0, const float* __restrict__ bias1,
               const float* __restrict__ resid, float* __restrict__ outp, int M) {
    __shared__ float As[2][128 * ASTR];
    __shared__ float Bsm[2][16 * BSTR];

    const int tid  = threadIdx.x;
    const int lane = tid & 31, warp = tid >> 5;
    const int wm = warp & 1, wn = warp >> 1;
    const int bm = blockIdx.y, bn = blockIdx.x;

    const float* Bmat;
    int ldb, bcol, ldo;
    bool isGate;
    float* out;
    if (EPI == 1) {
        ldo = 4096;
        out = g_proj;                 // device-side symbol reference (the fix)
        isGate = (bn * 128 < 1024);
        if (isGate) { Bmat = B0; ldb = 1024; bcol = bn * 128; }
        else        { Bmat = B1; ldb = 3072; bcol = bn * 128 - 1024; }
    } else {
        ldo = 1024; isGate = false;
        out = outp;
        Bmat = B0; ldb = 1024; bcol = bn * 128;
    }

    // loader indices
    const int arow = tid >> 2;   // 0..63 (+64 for second half)
    const int ac4  = tid & 3;    // float4 within 16-col row
    const int brow = tid >> 5;   // 0..7 (+8)
    const int bc4  = tid & 31;   // float4 along N

    const float* gA = g_xn + (size_t)(bm * 128 + arow) * 1024 + ac4 * 4;
    const float* gB = Bmat + (size_t)brow * ldb + bcol + bc4 * 4;

    uint32_t sA = (uint32_t)__cvta_generic_to_shared(&As[0][0]);
    uint32_t sB = (uint32_t)__cvta_generic_to_shared(&Bsm[0][0]);

    float c[4][4][4];
    #pragma unroll
    for (int i = 0; i < 4; i++)
        #pragma unroll
        for (int j = 0; j < 4; j++)
            #pragma unroll
            for (int k = 0; k < 4; k++) c[i][j][k] = 0.0f;

    const int KT = 64;  // 1024 / 16

    // prefetch tile 0 into buffer 0
    #pragma unroll
    for (int j = 0; j < 2; j++)
        cpasync16(sA + ((arow + 64 * j) * ASTR + ac4 * 4) * 4, gA + (size_t)(64 * j) * 1024);
    #pragma unroll
    for (int j = 0; j < 2; j++)
        cpasync16(sB + ((brow + 8 * j) * BSTR + bc4 * 4) * 4, gB + (size_t)(8 * j) * ldb);
    asm volatile("cp.async.commit_group;");

    for (int kt = 0; kt < KT; kt++) {
        asm volatile("cp.async.wait_group 0;");
        __syncthreads();

        if (kt + 1 < KT) {
            const int nb = (kt + 1) & 1;
            const float* ga = gA + (kt + 1) * 16;
            const float* gb = gB + (size_t)(kt + 1) * 16 * ldb;
            #pragma unroll
            for (int j = 0; j < 2; j++)
                cpasync16(sA + (nb * 128 * ASTR + (arow + 64 * j) * ASTR + ac4 * 4) * 4,
                          ga + (size_t)(64 * j) * 1024);
            #pragma unroll
            for (int j = 0; j < 2; j++)
                cpasync16(sB + (nb * 16 * BSTR + (brow + 8 * j) * BSTR + bc4 * 4) * 4,
                          gb + (size_t)(8 * j) * ldb);
        }
        asm volatile("cp.async.commit_group;");

        const int buf = kt & 1;
        const float* Ab = &As[buf][0];
        const float* Bb = &Bsm[buf][0];

        #pragma unroll
        for (int ks = 0; ks < 2; ks++) {
            uint32_t af[4][4], bf[4][2];
            const int r0 = wm * 64 + (lane >> 2);
            const int cc = ks * 8 + (lane & 3);
            #pragma unroll
            for (int mt = 0; mt < 4; mt++) {
                const float* ap = Ab + (r0 + mt * 16) * ASTR + cc;
                af[mt][0] = f2tf32(ap[0]);
                af[mt][1] = f2tf32(ap[8 * ASTR]);
                af[mt][2] = f2tf32(ap[4]);
                af[mt][3] = f2tf32(ap[8 * ASTR + 4]);
            }
            const int kr  = ks * 8 + (lane & 3);
            const int nb0 = wn * 32 + (lane >> 2);
            #pragma unroll
            for (int nt = 0; nt < 4; nt++) {
                const float* bp2 = Bb + kr * BSTR + nb0 + nt * 8;
                bf[nt][0] = f2tf32(bp2[0]);
                bf[nt][1] = f2tf32(bp2[4 * BSTR]);
            }
            #pragma unroll
            for (int mt = 0; mt < 4; mt++)
                #pragma unroll
                for (int nt = 0; nt < 4; nt++)
                    mma8(c[mt][nt], af[mt][0], af[mt][1], af[mt][2], af[mt][3],
                         bf[nt][0], bf[nt][1]);
        }
    }

    // epilogue
    #pragma unroll
    for (int mt = 0; mt < 4; mt++) {
        const int rbase = bm * 128 + wm * 64 + mt * 16 + (lane >> 2);
        #pragma unroll
        for (int nt = 0; nt < 4; nt++) {
            const int col0 = bn * 128 + wn * 32 + nt * 8 + (lane & 3) * 2;
            float b0v, b1v;
            bool sg;
            if (EPI == 1) {
                if (isGate) { b0v = bias0[col0]; b1v = bias0[col0 + 1]; sg = true; }
                else {
                    b0v = bias1[col0 - 1024]; b1v = bias1[col0 - 1023];
                    sg = (((col0 - 1024) % 192) < 64);   // delta columns
                }
            } else {
                b0v = bias0[col0]; b1v = bias0[col0 + 1]; sg = false;
            }
            #pragma unroll
            for (int half = 0; half < 2; half++) {
                const int row = rbase + 8 * half;
                float v0 = c[mt][nt][2 * half]     + b0v;
                float v1 = c[mt][nt][2 * half + 1] + b1v;
                if (EPI == 2) {
                    const float2 rr = *(const float2*)(resid + (size_t)row * 1024 + col0);
                    v0 += rr.x; v1 += rr.y;
                } else if (sg) {
                    v0 = sigmoidf_(v0); v1 = sigmoidf_(v1);
                }
                float2 st; st.x = v0; st.y = v1;
                *(float2*)(out + (size_t)row * ldo + col0) = st;
            }
        }
    }
}

// ---------------------------------------------------------------------------
// Fused scan: h = delta*h + B; ssm = C*h; mixed = g*ssm + (1-g)*xn (in place)
// 4096 threads = channels (b,h,d); 128 blocks x 32 threads to spread across SMs.
__global__ void scan_kernel(const float* __restrict__ state0,
                            float* __restrict__ state_out, int S) {
    const int t  = blockIdx.x * blockDim.x + threadIdx.x;  // 0..4095
    const int b  = t >> 10;
    const int hd = t & 1023;
    const int hh = hd >> 6;
    const int d  = hd & 63;
    const float* prow = g_proj + (size_t)b * S * 4096;
    const int off_g = hd;
    const int off_d = 1024 + hh * 192 + d;
    float* xr = g_xn + (size_t)b * S * 1024 + hd;
    float h = state0[t];
    #pragma unroll 8
    for (int s = 0; s < S; s++) {
        const float* row = prow + (size_t)s * 4096;
        const float delta = row[off_d];
        const float Bv    = row[off_d + 64];
        const float Cv    = row[off_d + 128];
        const float g     = row[off_g];
        h = fmaf(delta, h, Bv);
        const float ssm = Cv * h;
        const float xv  = xr[(size_t)s * 1024];
        xr[(size_t)s * 1024] = fmaf(g, ssm - xv, xv);
    }
    if (state_out) state_out[t] = h;
}

// ---------------------------------------------------------------------------
extern "C" void kernel_launch(void* const* d_in, const int* in_sizes, int n_in,
                              void* d_out, int out_size) {
    const float* x      = (const float*)d_in[0];
    const float* state  = (const float*)d_in[1];
    const float* norm_w = (const float*)d_in[2];
    const float* Wp     = (const float*)d_in[3];
    const float* bp     = (const float*)d_in[4];
    const float* Wg     = (const float*)d_in[5];
    const float* bg     = (const float*)d_in[6];
    const float* Wo     = (const float*)d_in[7];
    const float* bo     = (const float*)d_in[8];
    float* out = (float*)d_out;

    const int M = in_sizes[0] / 1024;  // B*S tokens (16384)
    const int S = M / 4;               // B = 4

    rmsnorm_kernel<<<M, 256>>>(x, norm_w);

    gemm_tf32<1><<<dim3(32, M / 128), 256>>>(Wg, Wp, bg, bp, nullptr, nullptr, M);

    float* state_out = nullptr;
    if (out_size >= M * 1024 + 4096) state_out = out + (size_t)M * 1024;
    scan_kernel<<<128, 32>>>(state, state_out, S);

    gemm_tf32<2><<<dim3(8, M / 128), 256>>>(Wo, nullptr, bo, nullptr, x, out, M);
}

// round 5
// speedup vs baseline: 1.8979x; 1.8979x over previous
#include <cuda_runtime.h>
#include <cstdint>

// ---------------------------------------------------------------------------
// MambaBlock: rmsnorm -> [gate|p] GEMM (tf32 mma) -> fused scan -> out GEMM
// Shapes: B=4, S=4096, D=1024, H=16, Dstate=64
// ---------------------------------------------------------------------------

#define MAX_M 16384

// scratch (device globals; referenced ONLY from device code)
__device__ float g_xn[(size_t)MAX_M * 1024];     // xn (tf32-rounded), later "mixed"
__device__ float g_proj[(size_t)MAX_M * 4096];   // [gate(1024) | p(3072)] per token
__device__ float g_wg[(size_t)1024 * 1024];      // tf32-rounded Wg
__device__ float g_wp[(size_t)1024 * 3072];      // tf32-rounded Wp
__device__ float g_wo[(size_t)1024 * 1024];      // tf32-rounded Wo

// ---------------------------------------------------------------------------
__device__ __forceinline__ uint32_t f2tf32(float x) {
    uint32_t r;
    asm("cvt.rna.tf32.f32 %0, %1;" : "=r"(r) : "f"(x));
    return r;
}
__device__ __forceinline__ void mma8(float* c,
                                     uint32_t a0, uint32_t a1, uint32_t a2, uint32_t a3,
                                     uint32_t b0, uint32_t b1) {
    asm volatile(
        "mma.sync.aligned.m16n8k8.row.col.f32.tf32.tf32.f32 "
        "{%0,%1,%2,%3},{%4,%5,%6,%7},{%8,%9},{%0,%1,%2,%3};"
        : "+f"(c[0]), "+f"(c[1]), "+f"(c[2]), "+f"(c[3])
        : "r"(a0), "r"(a1), "r"(a2), "r"(a3), "r"(b0), "r"(b1));
}
__device__ __forceinline__ void cpasync16(uint32_t saddr, const void* g) {
    asm volatile("cp.async.cg.shared.global [%0], [%1], 16;" :: "r"(saddr), "l"(g));
}
__device__ __forceinline__ float sigmoidf_(float v) {
    return 1.0f / (1.0f + __expf(-v));
}

// ---------------------------------------------------------------------------
// Pre-round all weights to tf32 (removes cvt from GEMM mainloop).
// 5M floats total as float4s: Wg 256K, Wp 768K, Wo 256K (float4 counts).
__global__ void round_weights_kernel(const float* __restrict__ Wg,
                                     const float* __restrict__ Wp,
                                     const float* __restrict__ Wo) {
    const int i = blockIdx.x * blockDim.x + threadIdx.x;  // float4 index
    const int NG = 256 * 1024;          // Wg float4s
    const int NP = 768 * 1024;          // Wp float4s
    const float4* src;
    float4* dst;
    int j;
    if (i < NG)            { src = (const float4*)Wg; dst = (float4*)g_wg; j = i; }
    else if (i < NG + NP)  { src = (const float4*)Wp; dst = (float4*)g_wp; j = i - NG; }
    else                   { src = (const float4*)Wo; dst = (float4*)g_wo; j = i - NG - NP; }
    float4 v = src[j];
    v.x = __uint_as_float(f2tf32(v.x));
    v.y = __uint_as_float(f2tf32(v.y));
    v.z = __uint_as_float(f2tf32(v.z));
    v.w = __uint_as_float(f2tf32(v.w));
    dst[j] = v;
}

// ---------------------------------------------------------------------------
// RMSNorm: one block per token, 256 threads x float4; stores tf32-rounded xn.
__global__ void rmsnorm_kernel(const float* __restrict__ x, const float* __restrict__ w) {
    const int row = blockIdx.x;
    const int tid = threadIdx.x;
    const float4* xr = (const float4*)(x + (size_t)row * 1024);
    float4 v = xr[tid];
    float ss = v.x * v.x + v.y * v.y + v.z * v.z + v.w * v.w;
    #pragma unroll
    for (int o = 16; o; o >>= 1) ss += __shfl_xor_sync(0xffffffff, ss, o);
    __shared__ float sred[8];
    const int lane = tid & 31, warp = tid >> 5;
    if (lane == 0) sred[warp] = ss;
    __syncthreads();
    if (warp == 0) {
        float t = sred[lane & 7];
        #pragma unroll
        for (int o = 4; o; o >>= 1) t += __shfl_xor_sync(0xffffffff, t, o);
        if (lane == 0) sred[0] = t;
    }
    __syncthreads();
    const float rinv = rsqrtf(sred[0] * (1.0f / 1024.0f) + 1e-6f);
    const float4 wv = ((const float4*)w)[tid];
    float4 o;
    o.x = __uint_as_float(f2tf32(v.x * rinv * wv.x));
    o.y = __uint_as_float(f2tf32(v.y * rinv * wv.y));
    o.z = __uint_as_float(f2tf32(v.z * rinv * wv.z));
    o.w = __uint_as_float(f2tf32(v.w * rinv * wv.w));
    ((float4*)(g_xn + (size_t)row * 1024))[tid] = o;
}

// ---------------------------------------------------------------------------
// TF32 GEMM, BM=BN=128, BK=16, 256 threads, warp tile 64x32 (mma m16n8k8).
// All operands pre-rounded to tf32 -> fragment loads are raw bit loads.
// EPI==1: A=g_xn, B=[g_wg | g_wp] split at col 1024, +bias, sigmoid on gate
//         and delta cols, out = g_proj (ld 4096).
// EPI==2: A=g_xn(mixed), B=g_wo, +bo + residual x, out = d_out (ld 1024).
constexpr int ASTR = 20;   // A smem stride (16 + 4 pad)
constexpr int BSTR = 136;  // B smem stride (128 + 8 pad)

template<int EPI>
__global__ __launch_bounds__(256, 2)
void gemm_tf32(const float* __restrict__ bias0, const float* __restrict__ bias1,
               const float* __restrict__ resid, float* __restrict__ outp, int M) {
    __shared__ float As[2][128 * ASTR];
    __shared__ float Bsm[2][16 * BSTR];

    const int tid  = threadIdx.x;
    const int lane = tid & 31, warp = tid >> 5;
    const int wm = warp & 1, wn = warp >> 1;
    const int bm = blockIdx.y, bn = blockIdx.x;

    const float* Bmat;
    int ldb, bcol, ldo;
    bool isGate;
    float* out;
    if (EPI == 1) {
        ldo = 4096;
        out = g_proj;
        isGate = (bn * 128 < 1024);
        if (isGate) { Bmat = g_wg; ldb = 1024; bcol = bn * 128; }
        else        { Bmat = g_wp; ldb = 3072; bcol = bn * 128 - 1024; }
    } else {
        ldo = 1024; isGate = false;
        out = outp;
        Bmat = g_wo; ldb = 1024; bcol = bn * 128;
    }

    const int arow = tid >> 2;   // 0..63 (+64)
    const int ac4  = tid & 3;
    const int brow = tid >> 5;   // 0..7 (+8)
    const int bc4  = tid & 31;

    const float* gA = g_xn + (size_t)(bm * 128 + arow) * 1024 + ac4 * 4;
    const float* gB = Bmat + (size_t)brow * ldb + bcol + bc4 * 4;

    uint32_t sA = (uint32_t)__cvta_generic_to_shared(&As[0][0]);
    uint32_t sB = (uint32_t)__cvta_generic_to_shared(&Bsm[0][0]);

    float c[4][4][4];
    #pragma unroll
    for (int i = 0; i < 4; i++)
        #pragma unroll
        for (int j = 0; j < 4; j++)
            #pragma unroll
            for (int k = 0; k < 4; k++) c[i][j][k] = 0.0f;

    const int KT = 64;  // 1024 / 16

    #pragma unroll
    for (int j = 0; j < 2; j++)
        cpasync16(sA + ((arow + 64 * j) * ASTR + ac4 * 4) * 4, gA + (size_t)(64 * j) * 1024);
    #pragma unroll
    for (int j = 0; j < 2; j++)
        cpasync16(sB + ((brow + 8 * j) * BSTR + bc4 * 4) * 4, gB + (size_t)(8 * j) * ldb);
    asm volatile("cp.async.commit_group;");

    for (int kt = 0; kt < KT; kt++) {
        asm volatile("cp.async.wait_group 0;");
        __syncthreads();

        if (kt + 1 < KT) {
            const int nb = (kt + 1) & 1;
            const float* ga = gA + (kt + 1) * 16;
            const float* gb = gB + (size_t)(kt + 1) * 16 * ldb;
            #pragma unroll
            for (int j = 0; j < 2; j++)
                cpasync16(sA + (nb * 128 * ASTR + (arow + 64 * j) * ASTR + ac4 * 4) * 4,
                          ga + (size_t)(64 * j) * 1024);
            #pragma unroll
            for (int j = 0; j < 2; j++)
                cpasync16(sB + (nb * 16 * BSTR + (brow + 8 * j) * BSTR + bc4 * 4) * 4,
                          gb + (size_t)(8 * j) * ldb);
        }
        asm volatile("cp.async.commit_group;");

        const int buf = kt & 1;
        const float* Ab = &As[buf][0];
        const float* Bb = &Bsm[buf][0];

        #pragma unroll
        for (int ks = 0; ks < 2; ks++) {
            uint32_t af[4][4], bf[4][2];
            const int r0 = wm * 64 + (lane >> 2);
            const int cc = ks * 8 + (lane & 3);
            #pragma unroll
            for (int mt = 0; mt < 4; mt++) {
                const float* ap = Ab + (r0 + mt * 16) * ASTR + cc;
                af[mt][0] = __float_as_uint(ap[0]);
                af[mt][1] = __float_as_uint(ap[8 * ASTR]);
                af[mt][2] = __float_as_uint(ap[4]);
                af[mt][3] = __float_as_uint(ap[8 * ASTR + 4]);
            }
            const int kr  = ks * 8 + (lane & 3);
            const int nb0 = wn * 32 + (lane >> 2);
            #pragma unroll
            for (int nt = 0; nt < 4; nt++) {
                const float* bp2 = Bb + kr * BSTR + nb0 + nt * 8;
                bf[nt][0] = __float_as_uint(bp2[0]);
                bf[nt][1] = __float_as_uint(bp2[4 * BSTR]);
            }
            #pragma unroll
            for (int mt = 0; mt < 4; mt++)
                #pragma unroll
                for (int nt = 0; nt < 4; nt++)
                    mma8(c[mt][nt], af[mt][0], af[mt][1], af[mt][2], af[mt][3],
                         bf[nt][0], bf[nt][1]);
        }
    }

    // epilogue
    #pragma unroll
    for (int mt = 0; mt < 4; mt++) {
        const int rbase = bm * 128 + wm * 64 + mt * 16 + (lane >> 2);
        #pragma unroll
        for (int nt = 0; nt < 4; nt++) {
            const int col0 = bn * 128 + wn * 32 + nt * 8 + (lane & 3) * 2;
            float b0v, b1v;
            bool sg;
            if (EPI == 1) {
                if (isGate) { b0v = bias0[col0]; b1v = bias0[col0 + 1]; sg = true; }
                else {
                    b0v = bias1[col0 - 1024]; b1v = bias1[col0 - 1023];
                    sg = (((col0 - 1024) % 192) < 64);   // delta columns
                }
            } else {
                b0v = bias0[col0]; b1v = bias0[col0 + 1]; sg = false;
            }
            #pragma unroll
            for (int half = 0; half < 2; half++) {
                const int row = rbase + 8 * half;
                float v0 = c[mt][nt][2 * half]     + b0v;
                float v1 = c[mt][nt][2 * half + 1] + b1v;
                if (EPI == 2) {
                    const float2 rr = *(const float2*)(resid + (size_t)row * 1024 + col0);
                    v0 += rr.x; v1 += rr.y;
                } else if (sg) {
                    v0 = sigmoidf_(v0); v1 = sigmoidf_(v1);
                }
                float2 st; st.x = v0; st.y = v1;
                *(float2*)(out + (size_t)row * ldo + col0) = st;
            }
        }
    }
}

// ---------------------------------------------------------------------------
// Fused scan: h = delta*h + B; ssm = C*h; mixed = g*ssm + (1-g)*xn (in place,
// tf32-rounded). 4096 threads = channels; software-pipelined load groups of 8
// (2 groups in flight) so DRAM latency is amortized 8-16x.
__global__ __launch_bounds__(32) void scan_kernel(const float* __restrict__ state0,
                                                  float* __restrict__ state_out, int S) {
    const int t  = blockIdx.x * blockDim.x + threadIdx.x;  // 0..4095
    const int b  = t >> 10;
    const int hd = t & 1023;
    const int hh = hd >> 6;
    const int d  = hd & 63;
    const float* __restrict__ pg = g_proj + (size_t)b * S * 4096 + hd;
    const float* __restrict__ pd = g_proj + (size_t)b * S * 4096 + 1024 + hh * 192 + d;
    float* __restrict__ xr = g_xn + (size_t)b * S * 1024 + hd;

    float h = state0[t];

    constexpr int G = 8;
    float fD[2][G], fB[2][G], fC[2][G], fG[2][G], fX[2][G];

    #define SCAN_PREFETCH(bufi, s0)                                        \
        _Pragma("unroll")                                                  \
        for (int i = 0; i < G; i++) {                                      \
            const size_t ro = (size_t)((s0) + i) * 4096;                   \
            fD[bufi][i] = __ldg(pd + ro);                                  \
            fB[bufi][i] = __ldg(pd + ro + 64);                             \
            fC[bufi][i] = __ldg(pd + ro + 128);                            \
            fG[bufi][i] = __ldg(pg + ro);                                  \
            fX[bufi][i] = __ldg(xr + (size_t)((s0) + i) * 1024);           \
        }

    SCAN_PREFETCH(0, 0)
    SCAN_PREFETCH(1, G)

    const int NG = S / G;
    for (int gidx = 0; gidx < NG; gidx++) {
        const int buf = gidx & 1;
        float outv[G];
        #pragma unroll
        for (int i = 0; i < G; i++) {
            h = fmaf(fD[buf][i], h, fB[buf][i]);
            const float ssm = fC[buf][i] * h;
            const float xv  = fX[buf][i];
            outv[i] = fmaf(fG[buf][i], ssm - xv, xv);
        }
        if (gidx + 2 < NG) { SCAN_PREFETCH(buf, (gidx + 2) * G) }
        const int s0 = gidx * G;
        #pragma unroll
        for (int i = 0; i < G; i++)
            xr[(size_t)(s0 + i) * 1024] = __uint_as_float(f2tf32(outv[i]));
    }
    if (state_out) state_out[t] = h;
    #undef SCAN_PREFETCH
}

// ---------------------------------------------------------------------------
extern "C" void kernel_launch(void* const* d_in, const int* in_sizes, int n_in,
                              void* d_out, int out_size) {
    const float* x      = (const float*)d_in[0];
    const float* state  = (const float*)d_in[1];
    const float* norm_w = (const float*)d_in[2];
    const float* Wp     = (const float*)d_in[3];
    const float* bp     = (const float*)d_in[4];
    const float* Wg     = (const float*)d_in[5];
    const float* bg     = (const float*)d_in[6];
    const float* Wo     = (const float*)d_in[7];
    const float* bo     = (const float*)d_in[8];
    float* out = (float*)d_out;

    const int M = in_sizes[0] / 1024;  // B*S tokens (16384)
    const int S = M / 4;               // B = 4

    round_weights_kernel<<<(5 * 256 * 1024 + 255) / 256, 256>>>(Wg, Wp, Wo);
    rmsnorm_kernel<<<M, 256>>>(x, norm_w);

    gemm_tf32<1><<<dim3(32, M / 128), 256>>>(bg, bp, nullptr, nullptr, M);

    float* state_out = nullptr;
    if (out_size >= M * 1024 + 4096) state_out = out + (size_t)M * 1024;
    scan_kernel<<<128, 32>>>(state, state_out, S);

    gemm_tf32<2><<<dim3(8, M / 128), 256>>>(bo, nullptr, x, out, M);
}

// round 6
// speedup vs baseline: 2.8588x; 1.5063x over previous
#include <cuda_runtime.h>
#include <cstdint>

// ---------------------------------------------------------------------------
// MambaBlock: rmsnorm -> [gate|p] GEMM (tf32 mma) -> chunked scan -> out GEMM
// Shapes: B=4, S=4096, D=1024, H=16, Dstate=64
// ---------------------------------------------------------------------------

#define MAX_M 16384
#define NCH   4096        // B * N_HEADS * D_STATE channels
#define CHUNKS 64         // time chunks for parallel scan

// scratch (device globals; referenced ONLY from device code)
__device__ float g_xn[(size_t)MAX_M * 1024];     // xn (tf32-rounded), later "mixed"
__device__ float g_proj[(size_t)MAX_M * 4096];   // [gate(1024) | p(3072)] per token
__device__ float g_wg[(size_t)1024 * 1024];      // tf32-rounded Wg
__device__ float g_wp[(size_t)1024 * 3072];      // tf32-rounded Wp
__device__ float g_wo[(size_t)1024 * 1024];      // tf32-rounded Wo
__device__ float g_cA[NCH * CHUNKS];             // per-chunk decay product
__device__ float g_cB[NCH * CHUNKS];             // per-chunk zero-input response
__device__ float g_hin[NCH * CHUNKS];            // per-chunk entry state

// ---------------------------------------------------------------------------
__device__ __forceinline__ uint32_t f2tf32(float x) {
    uint32_t r;
    asm("cvt.rna.tf32.f32 %0, %1;" : "=r"(r) : "f"(x));
    return r;
}
__device__ __forceinline__ void mma8(float* c,
                                     uint32_t a0, uint32_t a1, uint32_t a2, uint32_t a3,
                                     uint32_t b0, uint32_t b1) {
    asm volatile(
        "mma.sync.aligned.m16n8k8.row.col.f32.tf32.tf32.f32 "
        "{%0,%1,%2,%3},{%4,%5,%6,%7},{%8,%9},{%0,%1,%2,%3};"
        : "+f"(c[0]), "+f"(c[1]), "+f"(c[2]), "+f"(c[3])
        : "r"(a0), "r"(a1), "r"(a2), "r"(a3), "r"(b0), "r"(b1));
}
__device__ __forceinline__ void cpasync16(uint32_t saddr, const void* g) {
    asm volatile("cp.async.cg.shared.global [%0], [%1], 16;" :: "r"(saddr), "l"(g));
}
__device__ __forceinline__ float sigmoidf_(float v) {
    return 1.0f / (1.0f + __expf(-v));
}

// ---------------------------------------------------------------------------
// Pre-round all weights to tf32 (removes cvt from GEMM mainloop).
__global__ void round_weights_kernel(const float* __restrict__ Wg,
                                     const float* __restrict__ Wp,
                                     const float* __restrict__ Wo) {
    const int i = blockIdx.x * blockDim.x + threadIdx.x;  // float4 index
    const int NG = 256 * 1024;
    const int NP = 768 * 1024;
    const float4* src;
    float4* dst;
    int j;
    if (i < NG)            { src = (const float4*)Wg; dst = (float4*)g_wg; j = i; }
    else if (i < NG + NP)  { src = (const float4*)Wp; dst = (float4*)g_wp; j = i - NG; }
    else                   { src = (const float4*)Wo; dst = (float4*)g_wo; j = i - NG - NP; }
    float4 v = src[j];
    v.x = __uint_as_float(f2tf32(v.x));
    v.y = __uint_as_float(f2tf32(v.y));
    v.z = __uint_as_float(f2tf32(v.z));
    v.w = __uint_as_float(f2tf32(v.w));
    dst[j] = v;
}

// ---------------------------------------------------------------------------
// RMSNorm: one block per token, 256 threads x float4; stores tf32-rounded xn.
__global__ void rmsnorm_kernel(const float* __restrict__ x, const float* __restrict__ w) {
    const int row = blockIdx.x;
    const int tid = threadIdx.x;
    const float4* xr = (const float4*)(x + (size_t)row * 1024);
    float4 v = xr[tid];
    float ss = v.x * v.x + v.y * v.y + v.z * v.z + v.w * v.w;
    #pragma unroll
    for (int o = 16; o; o >>= 1) ss += __shfl_xor_sync(0xffffffff, ss, o);
    __shared__ float sred[8];
    const int lane = tid & 31, warp = tid >> 5;
    if (lane == 0) sred[warp] = ss;
    __syncthreads();
    if (warp == 0) {
        float t = sred[lane & 7];
        #pragma unroll
        for (int o = 4; o; o >>= 1) t += __shfl_xor_sync(0xffffffff, t, o);
        if (lane == 0) sred[0] = t;
    }
    __syncthreads();
    const float rinv = rsqrtf(sred[0] * (1.0f / 1024.0f) + 1e-6f);
    const float4 wv = ((const float4*)w)[tid];
    float4 o;
    o.x = __uint_as_float(f2tf32(v.x * rinv * wv.x));
    o.y = __uint_as_float(f2tf32(v.y * rinv * wv.y));
    o.z = __uint_as_float(f2tf32(v.z * rinv * wv.z));
    o.w = __uint_as_float(f2tf32(v.w * rinv * wv.w));
    ((float4*)(g_xn + (size_t)row * 1024))[tid] = o;
}

// ---------------------------------------------------------------------------
// TF32 GEMM, BM=BN=128, BK=16, 256 threads, warp tile 64x32 (mma m16n8k8).
constexpr int ASTR = 20;
constexpr int BSTR = 136;

template<int EPI>
__global__ __launch_bounds__(256, 2)
void gemm_tf32(const float* __restrict__ bias0, const float* __restrict__ bias1,
               const float* __restrict__ resid, float* __restrict__ outp, int M) {
    __shared__ float As[2][128 * ASTR];
    __shared__ float Bsm[2][16 * BSTR];

    const int tid  = threadIdx.x;
    const int lane = tid & 31, warp = tid >> 5;
    const int wm = warp & 1, wn = warp >> 1;
    const int bm = blockIdx.y, bn = blockIdx.x;

    const float* Bmat;
    int ldb, bcol, ldo;
    bool isGate;
    float* out;
    if (EPI == 1) {
        ldo = 4096;
        out = g_proj;
        isGate = (bn * 128 < 1024);
        if (isGate) { Bmat = g_wg; ldb = 1024; bcol = bn * 128; }
        else        { Bmat = g_wp; ldb = 3072; bcol = bn * 128 - 1024; }
    } else {
        ldo = 1024; isGate = false;
        out = outp;
        Bmat = g_wo; ldb = 1024; bcol = bn * 128;
    }

    const int arow = tid >> 2;
    const int ac4  = tid & 3;
    const int brow = tid >> 5;
    const int bc4  = tid & 31;

    const float* gA = g_xn + (size_t)(bm * 128 + arow) * 1024 + ac4 * 4;
    const float* gB = Bmat + (size_t)brow * ldb + bcol + bc4 * 4;

    uint32_t sA = (uint32_t)__cvta_generic_to_shared(&As[0][0]);
    uint32_t sB = (uint32_t)__cvta_generic_to_shared(&Bsm[0][0]);

    float c[4][4][4];
    #pragma unroll
    for (int i = 0; i < 4; i++)
        #pragma unroll
        for (int j = 0; j < 4; j++)
            #pragma unroll
            for (int k = 0; k < 4; k++) c[i][j][k] = 0.0f;

    const int KT = 64;

    #pragma unroll
    for (int j = 0; j < 2; j++)
        cpasync16(sA + ((arow + 64 * j) * ASTR + ac4 * 4) * 4, gA + (size_t)(64 * j) * 1024);
    #pragma unroll
    for (int j = 0; j < 2; j++)
        cpasync16(sB + ((brow + 8 * j) * BSTR + bc4 * 4) * 4, gB + (size_t)(8 * j) * ldb);
    asm volatile("cp.async.commit_group;");

    for (int kt = 0; kt < KT; kt++) {
        asm volatile("cp.async.wait_group 0;");
        __syncthreads();

        if (kt + 1 < KT) {
            const int nb = (kt + 1) & 1;
            const float* ga = gA + (kt + 1) * 16;
            const float* gb = gB + (size_t)(kt + 1) * 16 * ldb;
            #pragma unroll
            for (int j = 0; j < 2; j++)
                cpasync16(sA + (nb * 128 * ASTR + (arow + 64 * j) * ASTR + ac4 * 4) * 4,
                          ga + (size_t)(64 * j) * 1024);
            #pragma unroll
            for (int j = 0; j < 2; j++)
                cpasync16(sB + (nb * 16 * BSTR + (brow + 8 * j) * BSTR + bc4 * 4) * 4,
                          gb + (size_t)(8 * j) * ldb);
        }
        asm volatile("cp.async.commit_group;");

        const int buf = kt & 1;
        const float* Ab = &As[buf][0];
        const float* Bb = &Bsm[buf][0];

        #pragma unroll
        for (int ks = 0; ks < 2; ks++) {
            uint32_t af[4][4], bf[4][2];
            const int r0 = wm * 64 + (lane >> 2);
            const int cc = ks * 8 + (lane & 3);
            #pragma unroll
            for (int mt = 0; mt < 4; mt++) {
                const float* ap = Ab + (r0 + mt * 16) * ASTR + cc;
                af[mt][0] = __float_as_uint(ap[0]);
                af[mt][1] = __float_as_uint(ap[8 * ASTR]);
                af[mt][2] = __float_as_uint(ap[4]);
                af[mt][3] = __float_as_uint(ap[8 * ASTR + 4]);
            }
            const int kr  = ks * 8 + (lane & 3);
            const int nb0 = wn * 32 + (lane >> 2);
            #pragma unroll
            for (int nt = 0; nt < 4; nt++) {
                const float* bp2 = Bb + kr * BSTR + nb0 + nt * 8;
                bf[nt][0] = __float_as_uint(bp2[0]);
                bf[nt][1] = __float_as_uint(bp2[4 * BSTR]);
            }
            #pragma unroll
            for (int mt = 0; mt < 4; mt++)
                #pragma unroll
                for (int nt = 0; nt < 4; nt++)
                    mma8(c[mt][nt], af[mt][0], af[mt][1], af[mt][2], af[mt][3],
                         bf[nt][0], bf[nt][1]);
        }
    }

    #pragma unroll
    for (int mt = 0; mt < 4; mt++) {
        const int rbase = bm * 128 + wm * 64 + mt * 16 + (lane >> 2);
        #pragma unroll
        for (int nt = 0; nt < 4; nt++) {
            const int col0 = bn * 128 + wn * 32 + nt * 8 + (lane & 3) * 2;
            float b0v, b1v;
            bool sg;
            if (EPI == 1) {
                if (isGate) { b0v = bias0[col0]; b1v = bias0[col0 + 1]; sg = true; }
                else {
                    b0v = bias1[col0 - 1024]; b1v = bias1[col0 - 1023];
                    sg = (((col0 - 1024) % 192) < 64);   // delta columns
                }
            } else {
                b0v = bias0[col0]; b1v = bias0[col0 + 1]; sg = false;
            }
            #pragma unroll
            for (int half = 0; half < 2; half++) {
                const int row = rbase + 8 * half;
                float v0 = c[mt][nt][2 * half]     + b0v;
                float v1 = c[mt][nt][2 * half + 1] + b1v;
                if (EPI == 2) {
                    const float2 rr = *(const float2*)(resid + (size_t)row * 1024 + col0);
                    v0 += rr.x; v1 += rr.y;
                } else if (sg) {
                    v0 = sigmoidf_(v0); v1 = sigmoidf_(v1);
                }
                float2 st; st.x = v0; st.y = v1;
                *(float2*)(out + (size_t)row * ldo + col0) = st;
            }
        }
    }
}

// ---------------------------------------------------------------------------
// Chunked parallel scan over time.
// gid = c*NCH + t : lanes are consecutive channels (coalesced), c = chunk.

// Pass 1: per (channel, chunk) compute A = prod(delta), Bc = zero-input response.
__global__ __launch_bounds__(256) void scan_pass1(int S, int L) {
    const int gid = blockIdx.x * blockDim.x + threadIdx.x;
    const int t = gid & (NCH - 1);
    const int c = gid >> 12;
    const int b  = t >> 10;
    const int hd = t & 1023;
    const int hh = hd >> 6;
    const int d  = hd & 63;
    const float* __restrict__ pd = g_proj + (size_t)b * S * 4096 + 1024 + hh * 192 + d
                                   + (size_t)c * L * 4096;
    float A = 1.0f, h = 0.0f;
    #pragma unroll 8
    for (int s = 0; s < L; s++) {
        const float dl = pd[(size_t)s * 4096];
        const float bv = pd[(size_t)s * 4096 + 64];
        A *= dl;
        h = fmaf(dl, h, bv);
    }
    g_cA[gid] = A;
    g_cB[gid] = h;
}

// Pass 2: sequential combine across chunks per channel; record entry states.
__global__ __launch_bounds__(256) void scan_pass2(const float* __restrict__ state0,
                                                  float* __restrict__ state_out, int C) {
    const int t = blockIdx.x * blockDim.x + threadIdx.x;  // 0..NCH-1
    float h = state0[t];
    #pragma unroll 8
    for (int c = 0; c < C; c++) {
        g_hin[c * NCH + t] = h;
        h = fmaf(g_cA[c * NCH + t], h, g_cB[c * NCH + t]);
    }
    if (state_out) state_out[t] = h;
}

// Pass 3: rescan each chunk from exact h_in; fuse gate mix, write tf32 mixed.
__global__ __launch_bounds__(256) void scan_pass3(int S, int L) {
    const int gid = blockIdx.x * blockDim.x + threadIdx.x;
    const int t = gid & (NCH - 1);
    const int c = gid >> 12;
    const int b  = t >> 10;
    const int hd = t & 1023;
    const int hh = hd >> 6;
    const int d  = hd & 63;
    const size_t base = (size_t)b * S * 4096 + (size_t)c * L * 4096;
    const float* __restrict__ pd = g_proj + base + 1024 + hh * 192 + d;
    const float* __restrict__ pg = g_proj + base + hd;
    float* __restrict__ xr = g_xn + (size_t)b * S * 1024 + hd + (size_t)c * L * 1024;
    float h = g_hin[gid];
    #pragma unroll 4
    for (int s = 0; s < L; s++) {
        const float dl = pd[(size_t)s * 4096];
        const float bv = pd[(size_t)s * 4096 + 64];
        const float cv = pd[(size_t)s * 4096 + 128];
        const float g  = pg[(size_t)s * 4096];
        h = fmaf(dl, h, bv);
        const float ssm = cv * h;
        const float xv  = xr[(size_t)s * 1024];
        xr[(size_t)s * 1024] = __uint_as_float(f2tf32(fmaf(g, ssm - xv, xv)));
    }
}

// ---------------------------------------------------------------------------
extern "C" void kernel_launch(void* const* d_in, const int* in_sizes, int n_in,
                              void* d_out, int out_size) {
    const float* x      = (const float*)d_in[0];
    const float* state  = (const float*)d_in[1];
    const float* norm_w = (const float*)d_in[2];
    const float* Wp     = (const float*)d_in[3];
    const float* bp     = (const float*)d_in[4];
    const float* Wg     = (const float*)d_in[5];
    const float* bg     = (const float*)d_in[6];
    const float* Wo     = (const float*)d_in[7];
    const float* bo     = (const float*)d_in[8];
    float* out = (float*)d_out;

    const int M = in_sizes[0] / 1024;  // B*S tokens (16384)
    const int S = M / 4;               // B = 4
    const int L = S / CHUNKS;          // steps per chunk (64)

    round_weights_kernel<<<(5 * 256 * 1024 + 255) / 256, 256>>>(Wg, Wp, Wo);
    rmsnorm_kernel<<<M, 256>>>(x, norm_w);

    gemm_tf32<1><<<dim3(32, M / 128), 256>>>(bg, bp, nullptr, nullptr, M);

    float* state_out = nullptr;
    if (out_size >= M * 1024 + 4096) state_out = out + (size_t)M * 1024;

    scan_pass1<<<NCH * CHUNKS / 256, 256>>>(S, L);
    scan_pass2<<<NCH / 256, 256>>>(state, state_out, CHUNKS);
    scan_pass3<<<NCH * CHUNKS / 256, 256>>>(S, L);

    gemm_tf32<2><<<dim3(8, M / 128), 256>>>(bo, nullptr, x, out, M);
}